// round 4
// baseline (speedup 1.0000x reference)
#include <cuda_runtime.h>
#include <math.h>

#define NN  100000
#define EE  1600000
#define IND 512
#define HGD 64
#define OUTD 20

// ---------------- scratch (static device globals; no allocs) ----------------
__device__ float g_deg[NN];            // deg, then dinv (in place)
__device__ __align__(16) float g_xw[(size_t)NN * HGD];
__device__ __align__(16) float g_agg[(size_t)NN * HGD];
__device__ __align__(16) float g_h[(size_t)NN * HGD];
__device__ float g_norm[EE];
__device__ int   g_row[EE];
__device__ int   g_col[EE];

__device__ __forceinline__ float selu_f(float x) {
    const float a = 1.6732632423543772f, s = 1.0507009873554805f;
    return s * (x > 0.f ? x : a * expm1f(x));
}

// ---------------- degree / normalization ----------------
__global__ void k_deg_init() {
    int i = blockIdx.x * blockDim.x + threadIdx.x;
    if (i < NN) g_deg[i] = 1.0f;   // self-loop weight
}

// edge_index is INT32 (JAX downcasts int64 -> int32 without x64 mode)
__global__ void k_deg_acc(const int* __restrict__ ei, const float* __restrict__ w) {
    int e = blockIdx.x * blockDim.x + threadIdx.x;
    if (e < EE) {
        int c = ei[EE + e];
        atomicAdd(&g_deg[c], w[e]);
    }
}

__global__ void k_dinv() {
    int i = blockIdx.x * blockDim.x + threadIdx.x;
    if (i < NN) {
        float d = g_deg[i];
        g_deg[i] = d > 0.f ? rsqrtf(fmaxf(d, 1e-30f)) : 0.f;
    }
}

__global__ void k_prep(const int* __restrict__ ei, const float* __restrict__ w) {
    int e = blockIdx.x * blockDim.x + threadIdx.x;
    if (e < EE) {
        int r = ei[e];
        int c = ei[EE + e];
        g_row[e] = r;
        g_col[e] = c;
        g_norm[e] = g_deg[r] * w[e] * g_deg[c];
    }
}

// ---------------- GEMM: C[M,64] = A[M,K] @ B[K,64] ----------------
// 64-row tiles, 256 threads, 4x4 register micro-tile, K-tiles of 16.
__global__ void k_gemm64(const float* __restrict__ A, const float* __restrict__ B,
                         float* __restrict__ C, int M, int K) {
    __shared__ float As[16][68];   // [k][row], pad for banks
    __shared__ float Bs[16][64];   // [k][col]
    int tid = threadIdx.x;
    int tx = tid & 15, ty = tid >> 4;
    int row0 = blockIdx.x * 64;

    float acc[4][4] = {};

    for (int kt = 0; kt < K; kt += 16) {
#pragma unroll
        for (int j = 0; j < 4; j++) {
            int i = tid + 256 * j;
            int r = i >> 4, kk = i & 15;
            int row = row0 + r;
            As[kk][r] = (row < M) ? A[(size_t)row * K + kt + kk] : 0.f;
        }
#pragma unroll
        for (int j = 0; j < 4; j++) {
            int i = tid + 256 * j;
            int bk = i >> 6, bc = i & 63;
            Bs[bk][bc] = B[(size_t)(kt + bk) * 64 + bc];
        }
        __syncthreads();
#pragma unroll
        for (int kk = 0; kk < 16; kk++) {
            float4 a4 = *(const float4*)&As[kk][ty * 4];
            float4 b4 = *(const float4*)&Bs[kk][tx * 4];
            float av[4] = {a4.x, a4.y, a4.z, a4.w};
            float bv[4] = {b4.x, b4.y, b4.z, b4.w};
#pragma unroll
            for (int i = 0; i < 4; i++)
#pragma unroll
                for (int j = 0; j < 4; j++)
                    acc[i][j] += av[i] * bv[j];
        }
        __syncthreads();
    }
#pragma unroll
    for (int i = 0; i < 4; i++) {
        int row = row0 + ty * 4 + i;
        if (row < M) {
            float4 v = make_float4(acc[i][0], acc[i][1], acc[i][2], acc[i][3]);
            *(float4*)&C[(size_t)row * 64 + tx * 4] = v;
        }
    }
}

// ---------------- agg init with self-loop term: agg[i] = dinv[i]^2 * xw[i] ----
__global__ void k_selfinit() {
    int i = blockIdx.x * blockDim.x + threadIdx.x;   // over NN*16 float4s
    if (i < NN * 16) {
        int node = i >> 4;
        float d = g_deg[node];
        float dd = d * d;
        float4 v = ((const float4*)g_xw)[i];
        v.x *= dd; v.y *= dd; v.z *= dd; v.w *= dd;
        ((float4*)g_agg)[i] = v;
    }
}

// ---------------- edge scatter: agg[col] += norm * xw[row] ----------------
// 16 threads per edge, each handles one float4 of the 64-wide feature vector.
__global__ void k_scatter() {
    int t = blockIdx.x * blockDim.x + threadIdx.x;
    if (t >= EE * 16) return;
    int e = t >> 4;
    int q = (t & 15) << 2;
    int r = g_row[e], c = g_col[e];
    float nm = g_norm[e];
    float4 v = *(const float4*)&g_xw[(size_t)r * 64 + q];
    float* dst = &g_agg[(size_t)c * 64 + q];
    atomicAdd(dst + 0, nm * v.x);
    atomicAdd(dst + 1, nm * v.y);
    atomicAdd(dst + 2, nm * v.z);
    atomicAdd(dst + 3, nm * v.w);
}

// ---------------- bias + SELU: h = selu(agg + b) ----------------
__global__ void k_bias_selu(const float* __restrict__ b) {
    int i = blockIdx.x * blockDim.x + threadIdx.x;
    if (i < NN * HGD) {
        int f = i & 63;
        g_h[i] = selu_f(g_agg[i] + b[f]);
    }
}

// ---------------- fused dense MLP (3x 64x64 SELU + 64x20) + softmax --------
// 16 rows per block, 256 threads: thread (rq = tid>>6 owns 4 rows, j = tid&63).
__global__ void k_dense(const float* __restrict__ w0, const float* __restrict__ b0,
                        const float* __restrict__ w1, const float* __restrict__ b1,
                        const float* __restrict__ w2, const float* __restrict__ b2,
                        const float* __restrict__ w3, const float* __restrict__ b3,
                        float* __restrict__ out) {
    __shared__ float Ws[64][64];
    __shared__ float hs[16][64];
    __shared__ float lg[16][20];
    __shared__ float bs[64];

    int tid = threadIdx.x;
    int j = tid & 63, rq = tid >> 6;
    int row0 = blockIdx.x * 16;

    for (int i = tid; i < 16 * 64; i += 256) {
        int r = i >> 6, f = i & 63;
        int row = row0 + r;
        hs[r][f] = (row < NN) ? g_h[(size_t)row * 64 + f] : 0.f;
    }

    const float* Wp[3] = {w0, w1, w2};
    const float* Bp[3] = {b0, b1, b2};

    for (int L = 0; L < 3; L++) {
        __syncthreads();
        for (int i = tid; i < 4096; i += 256) Ws[i >> 6][i & 63] = Wp[L][i];
        if (tid < 64) bs[tid] = Bp[L][tid];
        __syncthreads();
        float acc[4];
#pragma unroll
        for (int i = 0; i < 4; i++) acc[i] = bs[j];
        for (int k = 0; k < 64; k++) {
            float wv = Ws[k][j];
#pragma unroll
            for (int i = 0; i < 4; i++) acc[i] += hs[rq * 4 + i][k] * wv;
        }
        __syncthreads();
#pragma unroll
        for (int i = 0; i < 4; i++) hs[rq * 4 + i][j] = selu_f(acc[i]);
    }

    // final layer: 64 -> 20 (no activation), then softmax
    __syncthreads();
    for (int i = tid; i < 64 * 20; i += 256) Ws[i / 20][i % 20] = w3[i];
    if (tid < 20) bs[tid] = b3[tid];
    __syncthreads();

    if (j < 20) {
        float acc[4];
#pragma unroll
        for (int i = 0; i < 4; i++) acc[i] = bs[j];
        for (int k = 0; k < 64; k++) {
            float wv = Ws[k][j];
#pragma unroll
            for (int i = 0; i < 4; i++) acc[i] += hs[rq * 4 + i][k] * wv;
        }
#pragma unroll
        for (int i = 0; i < 4; i++) lg[rq * 4 + i][j] = acc[i];
    }
    __syncthreads();

    for (int idx = tid; idx < 16 * 20; idx += 256) {
        int r = idx / 20, jj = idx % 20;
        int row = row0 + r;
        if (row < NN) {
            float mx = -1e30f;
#pragma unroll
            for (int k = 0; k < 20; k++) mx = fmaxf(mx, lg[r][k]);
            float s = 0.f;
#pragma unroll
            for (int k = 0; k < 20; k++) s += expf(lg[r][k] - mx);
            out[(size_t)row * 20 + jj] = expf(lg[r][jj] - mx) / s;
        }
    }
}

// ---------------- launch ----------------
extern "C" void kernel_launch(void* const* d_in, const int* in_sizes, int n_in,
                              void* d_out, int out_size) {
    const float* x    = (const float*)d_in[0];
    const int*   ei   = (const int*)d_in[1];      // int32! (JAX x64 disabled)
    const float* ea   = (const float*)d_in[2];
    const float* gc0w = (const float*)d_in[3];
    const float* gc0b = (const float*)d_in[4];
    const float* gc1w = (const float*)d_in[5];
    const float* gc1b = (const float*)d_in[6];
    const float* l0w  = (const float*)d_in[7];
    const float* l0b  = (const float*)d_in[8];
    const float* l1w  = (const float*)d_in[9];
    const float* l1b  = (const float*)d_in[10];
    const float* l2w  = (const float*)d_in[11];
    const float* l2b  = (const float*)d_in[12];
    const float* l3w  = (const float*)d_in[13];
    const float* l3b  = (const float*)d_in[14];
    float*       out  = (float*)d_out;

    float *xw, *h;
    cudaGetSymbolAddress((void**)&xw, g_xw);
    cudaGetSymbolAddress((void**)&h,  g_h);

    const int T = 256;

    k_deg_init<<<(NN + T - 1) / T, T>>>();
    k_deg_acc<<<(EE + T - 1) / T, T>>>(ei, ea);
    k_dinv<<<(NN + T - 1) / T, T>>>();
    k_prep<<<(EE + T - 1) / T, T>>>(ei, ea);

    // conv 0
    k_gemm64<<<(NN + 63) / 64, T>>>(x, gc0w, xw, NN, IND);
    k_selfinit<<<(NN * 16 + T - 1) / T, T>>>();
    k_scatter<<<(EE * 16 + T - 1) / T, T>>>();
    k_bias_selu<<<(NN * HGD + T - 1) / T, T>>>(gc0b);

    // conv 1
    k_gemm64<<<(NN + 63) / 64, T>>>(h, gc1w, xw, NN, HGD);
    k_selfinit<<<(NN * 16 + T - 1) / T, T>>>();
    k_scatter<<<(EE * 16 + T - 1) / T, T>>>();
    k_bias_selu<<<(NN * HGD + T - 1) / T, T>>>(gc1b);

    // dense stack + softmax
    k_dense<<<(NN + 15) / 16, T>>>(l0w, l0b, l1w, l1b, l2w, l2b, l3w, l3b, out);
}

// round 5
// speedup vs baseline: 1.3705x; 1.3705x over previous
#include <cuda_runtime.h>
#include <math.h>

#define NN  100000
#define EE  1600000
#define IND 512
#define HGD 64
#define OUTD 20

// ---------------- scratch (static device globals; no allocs) ----------------
__device__ float g_deg[NN];            // deg, then dinv (in place)
__device__ __align__(16) float g_xw[(size_t)NN * HGD];
__device__ __align__(16) float g_agg[(size_t)NN * HGD];
__device__ __align__(16) float g_h[(size_t)NN * HGD];
__device__ float g_norm[EE];
__device__ int   g_row[EE];
__device__ int   g_col[EE];

__device__ __forceinline__ float selu_f(float x) {
    const float a = 1.6732632423543772f, s = 1.0507009873554805f;
    return s * (x > 0.f ? x : a * expm1f(x));
}

// ---------------- degree / normalization ----------------
__global__ void k_deg_init() {
    int i = blockIdx.x * blockDim.x + threadIdx.x;
    if (i < NN) g_deg[i] = 1.0f;   // self-loop weight
}

__global__ void k_deg_acc(const int* __restrict__ ei, const float* __restrict__ w) {
    int e = blockIdx.x * blockDim.x + threadIdx.x;
    if (e < EE) atomicAdd(&g_deg[ei[EE + e]], w[e]);
}

__global__ void k_dinv() {
    int i = blockIdx.x * blockDim.x + threadIdx.x;
    if (i < NN) {
        float d = g_deg[i];
        g_deg[i] = d > 0.f ? rsqrtf(fmaxf(d, 1e-30f)) : 0.f;
    }
}

__global__ void k_prep(const int* __restrict__ ei, const float* __restrict__ w) {
    int e = blockIdx.x * blockDim.x + threadIdx.x;
    if (e < EE) {
        int r = ei[e];
        int c = ei[EE + e];
        g_row[e] = r;
        g_col[e] = c;
        g_norm[e] = g_deg[r] * w[e] * g_deg[c];
    }
}

// ---------------- GEMM: C[M,64] = A[M,K] @ B[K,64], fused selfinit epilogue --
// 128-row tiles, 256 threads, 8x4 register micro-tile, K-tiles of 16.
// Epilogue also writes g_agg[row] = dinv[row]^2 * C[row] (self-loop term).
__global__ void k_gemm128(const float* __restrict__ A, const float* __restrict__ B,
                          float* __restrict__ C, int M, int K) {
    __shared__ float As[16][128];  // [k][row]
    __shared__ float Bs[16][64];   // [k][col]
    int tid = threadIdx.x;
    int tx = tid & 15;             // col group: 4 cols
    int ty = tid >> 4;             // row group: 8 rows
    int row0 = blockIdx.x * 128;

    float acc[8][4] = {};

    for (int kt = 0; kt < K; kt += 16) {
        // load A tile: 128 rows x 16 k = 512 float4, 2 per thread, transpose-store
#pragma unroll
        for (int j = 0; j < 2; j++) {
            int f4 = tid * 2 + j;
            int r = f4 >> 2;             // 0..127
            int kq = (f4 & 3) * 4;       // 0,4,8,12
            int row = row0 + r;
            float4 v = (row < M) ? *(const float4*)&A[(size_t)row * K + kt + kq]
                                 : make_float4(0.f, 0.f, 0.f, 0.f);
            As[kq + 0][r] = v.x;
            As[kq + 1][r] = v.y;
            As[kq + 2][r] = v.z;
            As[kq + 3][r] = v.w;
        }
        // load B tile: 16 x 64 = 256 float4, 1 per thread
        {
            int bk = tid >> 4, bc = (tid & 15) * 4;
            *(float4*)&Bs[bk][bc] = *(const float4*)&B[(size_t)(kt + bk) * 64 + bc];
        }
        __syncthreads();
#pragma unroll
        for (int kk = 0; kk < 16; kk++) {
            float4 a0 = *(const float4*)&As[kk][ty * 8];
            float4 a1 = *(const float4*)&As[kk][ty * 8 + 4];
            float4 b  = *(const float4*)&Bs[kk][tx * 4];
            float av[8] = {a0.x, a0.y, a0.z, a0.w, a1.x, a1.y, a1.z, a1.w};
            float bv[4] = {b.x, b.y, b.z, b.w};
#pragma unroll
            for (int i = 0; i < 8; i++)
#pragma unroll
                for (int j = 0; j < 4; j++)
                    acc[i][j] += av[i] * bv[j];
        }
        __syncthreads();
    }
#pragma unroll
    for (int i = 0; i < 8; i++) {
        int row = row0 + ty * 8 + i;
        if (row < M) {
            float4 v = make_float4(acc[i][0], acc[i][1], acc[i][2], acc[i][3]);
            *(float4*)&C[(size_t)row * 64 + tx * 4] = v;
            float d = g_deg[row];
            float dd = d * d;
            float4 s = make_float4(v.x * dd, v.y * dd, v.z * dd, v.w * dd);
            *(float4*)&g_agg[(size_t)row * 64 + tx * 4] = s;
        }
    }
}

// ---------------- edge scatter: agg[col] += norm * xw[row] ----------------
// 16 threads per edge, one float4 each; vector reduction to L2.
__global__ void k_scatter() {
    int t = blockIdx.x * blockDim.x + threadIdx.x;
    if (t >= EE * 16) return;
    int e = t >> 4;
    int q = (t & 15) << 2;
    int r = g_row[e], c = g_col[e];
    float nm = g_norm[e];
    float4 v = *(const float4*)&g_xw[(size_t)r * 64 + q];
    float* dst = &g_agg[(size_t)c * 64 + q];
    asm volatile("red.global.add.v4.f32 [%0], {%1, %2, %3, %4};"
                 :: "l"(dst), "f"(nm * v.x), "f"(nm * v.y), "f"(nm * v.z), "f"(nm * v.w)
                 : "memory");
}

// ---------------- bias + SELU: h = selu(agg + b) ----------------
__global__ void k_bias_selu(const float* __restrict__ b) {
    int i = blockIdx.x * blockDim.x + threadIdx.x;
    if (i < NN * HGD) {
        int f = i & 63;
        g_h[i] = selu_f(g_agg[i] + b[f]);
    }
}

// ---------------- fused dense MLP (3x 64x64 SELU + 64x20) + softmax --------
__global__ void k_dense(const float* __restrict__ w0, const float* __restrict__ b0,
                        const float* __restrict__ w1, const float* __restrict__ b1,
                        const float* __restrict__ w2, const float* __restrict__ b2,
                        const float* __restrict__ w3, const float* __restrict__ b3,
                        float* __restrict__ out) {
    __shared__ float Ws[64][64];
    __shared__ float hs[16][64];
    __shared__ float lg[16][20];
    __shared__ float bs[64];

    int tid = threadIdx.x;
    int j = tid & 63, rq = tid >> 6;
    int row0 = blockIdx.x * 16;

    for (int i = tid; i < 16 * 64; i += 256) {
        int r = i >> 6, f = i & 63;
        int row = row0 + r;
        hs[r][f] = (row < NN) ? g_h[(size_t)row * 64 + f] : 0.f;
    }

    const float* Wp[3] = {w0, w1, w2};
    const float* Bp[3] = {b0, b1, b2};

    for (int L = 0; L < 3; L++) {
        __syncthreads();
        for (int i = tid; i < 4096; i += 256) Ws[i >> 6][i & 63] = Wp[L][i];
        if (tid < 64) bs[tid] = Bp[L][tid];
        __syncthreads();
        float acc[4];
#pragma unroll
        for (int i = 0; i < 4; i++) acc[i] = bs[j];
        for (int k = 0; k < 64; k++) {
            float wv = Ws[k][j];
#pragma unroll
            for (int i = 0; i < 4; i++) acc[i] += hs[rq * 4 + i][k] * wv;
        }
        __syncthreads();
#pragma unroll
        for (int i = 0; i < 4; i++) hs[rq * 4 + i][j] = selu_f(acc[i]);
    }

    __syncthreads();
    for (int i = tid; i < 64 * 20; i += 256) Ws[i / 20][i % 20] = w3[i];
    if (tid < 20) bs[tid] = b3[tid];
    __syncthreads();

    if (j < 20) {
        float acc[4];
#pragma unroll
        for (int i = 0; i < 4; i++) acc[i] = bs[j];
        for (int k = 0; k < 64; k++) {
            float wv = Ws[k][j];
#pragma unroll
            for (int i = 0; i < 4; i++) acc[i] += hs[rq * 4 + i][k] * wv;
        }
#pragma unroll
        for (int i = 0; i < 4; i++) lg[rq * 4 + i][j] = acc[i];
    }
    __syncthreads();

    for (int idx = tid; idx < 16 * 20; idx += 256) {
        int r = idx / 20, jj = idx % 20;
        int row = row0 + r;
        if (row < NN) {
            float mx = -1e30f;
#pragma unroll
            for (int k = 0; k < 20; k++) mx = fmaxf(mx, lg[r][k]);
            float s = 0.f;
#pragma unroll
            for (int k = 0; k < 20; k++) s += expf(lg[r][k] - mx);
            out[(size_t)row * 20 + jj] = expf(lg[r][jj] - mx) / s;
        }
    }
}

// ---------------- launch ----------------
extern "C" void kernel_launch(void* const* d_in, const int* in_sizes, int n_in,
                              void* d_out, int out_size) {
    const float* x    = (const float*)d_in[0];
    const int*   ei   = (const int*)d_in[1];      // int32 (JAX x64 disabled)
    const float* ea   = (const float*)d_in[2];
    const float* gc0w = (const float*)d_in[3];
    const float* gc0b = (const float*)d_in[4];
    const float* gc1w = (const float*)d_in[5];
    const float* gc1b = (const float*)d_in[6];
    const float* l0w  = (const float*)d_in[7];
    const float* l0b  = (const float*)d_in[8];
    const float* l1w  = (const float*)d_in[9];
    const float* l1b  = (const float*)d_in[10];
    const float* l2w  = (const float*)d_in[11];
    const float* l2b  = (const float*)d_in[12];
    const float* l3w  = (const float*)d_in[13];
    const float* l3b  = (const float*)d_in[14];
    float*       out  = (float*)d_out;

    float *xw, *h;
    cudaGetSymbolAddress((void**)&xw, g_xw);
    cudaGetSymbolAddress((void**)&h,  g_h);

    const int T = 256;

    k_deg_init<<<(NN + T - 1) / T, T>>>();
    k_deg_acc<<<(EE + T - 1) / T, T>>>(ei, ea);
    k_dinv<<<(NN + T - 1) / T, T>>>();
    k_prep<<<(EE + T - 1) / T, T>>>(ei, ea);

    // conv 0 (GEMM writes xw AND agg self-loop term)
    k_gemm128<<<(NN + 127) / 128, T>>>(x, gc0w, xw, NN, IND);
    k_scatter<<<(EE * 16 + T - 1) / T, T>>>();
    k_bias_selu<<<(NN * HGD + T - 1) / T, T>>>(gc0b);

    // conv 1
    k_gemm128<<<(NN + 127) / 128, T>>>(h, gc1w, xw, NN, HGD);
    k_scatter<<<(EE * 16 + T - 1) / T, T>>>();
    k_bias_selu<<<(NN * HGD + T - 1) / T, T>>>(gc1b);

    // dense stack + softmax
    k_dense<<<(NN + 15) / 16, T>>>(l0w, l0b, l1w, l1b, l2w, l2b, l3w, l3b, out);
}

// round 6
// speedup vs baseline: 1.6743x; 1.2217x over previous
#include <cuda_runtime.h>
#include <math.h>

#define NN  100000
#define EE  1600000
#define IND 512
#define HGD 64
#define OUTD 20

#define SCAN_BLK 1024
#define NBLK ((NN + SCAN_BLK - 1) / SCAN_BLK)   // 98

// ---------------- scratch (static device globals; no allocs) ----------------
__device__ float g_deg[NN];               // deg, then dinv (in place)
__device__ int   g_cnt[NN];               // in-degree count
__device__ int   g_rowptr[NN + 1];        // CSR offsets (by dst)
__device__ int   g_cursor[NN];            // fill cursors
__device__ int   g_bsum[NBLK];            // scan block sums
__device__ int   g_csrc[EE];              // CSR: source node per edge
__device__ float g_cnrm[EE];              // CSR: norm per edge
__device__ __align__(16) float g_xw[(size_t)NN * HGD];
__device__ __align__(16) float g_h[(size_t)NN * HGD];

__device__ __forceinline__ float selu_f(float x) {
    const float a = 1.6732632423543772f, s = 1.0507009873554805f;
    return s * (x > 0.f ? x : a * expm1f(x));
}

// ---------------- degree + count ----------------
__global__ void k_deg_init() {
    int i = blockIdx.x * blockDim.x + threadIdx.x;
    if (i < NN) { g_deg[i] = 1.0f; g_cnt[i] = 0; }   // self-loop weight 1
}

__global__ void k_deg_acc(const int* __restrict__ ei, const float* __restrict__ w) {
    int e = blockIdx.x * blockDim.x + threadIdx.x;
    if (e < EE) {
        int c = ei[EE + e];
        atomicAdd(&g_deg[c], w[e]);
        atomicAdd(&g_cnt[c], 1);
    }
}

__global__ void k_dinv() {
    int i = blockIdx.x * blockDim.x + threadIdx.x;
    if (i < NN) {
        float d = g_deg[i];
        g_deg[i] = d > 0.f ? rsqrtf(fmaxf(d, 1e-30f)) : 0.f;
    }
}

// ---------------- exclusive scan over g_cnt -> g_rowptr ----------------
__global__ void k_scan1() {
    __shared__ int sh[SCAN_BLK];
    int i = blockIdx.x * SCAN_BLK + threadIdx.x;
    int v = (i < NN) ? g_cnt[i] : 0;
    sh[threadIdx.x] = v;
    __syncthreads();
    for (int off = 1; off < SCAN_BLK; off <<= 1) {
        int t = (threadIdx.x >= off) ? sh[threadIdx.x - off] : 0;
        __syncthreads();
        sh[threadIdx.x] += t;
        __syncthreads();
    }
    if (i < NN) g_rowptr[i] = sh[threadIdx.x] - v;   // block-local exclusive
    if (threadIdx.x == SCAN_BLK - 1) g_bsum[blockIdx.x] = sh[threadIdx.x];
}

__global__ void k_scan_top() {
    __shared__ int sh[128];
    int t = threadIdx.x;
    int v = (t < NBLK) ? g_bsum[t] : 0;
    sh[t] = v;
    __syncthreads();
    for (int off = 1; off < 128; off <<= 1) {
        int u = (t >= off) ? sh[t - off] : 0;
        __syncthreads();
        sh[t] += u;
        __syncthreads();
    }
    if (t < NBLK) g_bsum[t] = sh[t] - v;   // exclusive
}

__global__ void k_scan_add() {
    int i = blockIdx.x * SCAN_BLK + threadIdx.x;
    if (i < NN) {
        int r = g_rowptr[i] + g_bsum[blockIdx.x];
        g_rowptr[i] = r;
        g_cursor[i] = r;
    }
    if (i == 0) g_rowptr[NN] = EE;
}

// ---------------- CSR fill ----------------
__global__ void k_fill(const int* __restrict__ ei, const float* __restrict__ w) {
    int e = blockIdx.x * blockDim.x + threadIdx.x;
    if (e < EE) {
        int r = ei[e];
        int c = ei[EE + e];
        int pos = atomicAdd(&g_cursor[c], 1);
        g_csrc[pos] = r;
        g_cnrm[pos] = g_deg[r] * w[e] * g_deg[c];
    }
}

// ---------------- GEMM: C[M,64] = A[M,K] @ B[K,64] ----------------
// 128-row tiles, 256 threads, 8x4 register micro-tile, K-tiles of 16.
__global__ void k_gemm128(const float* __restrict__ A, const float* __restrict__ B,
                          float* __restrict__ C, int M, int K) {
    __shared__ float As[16][128];  // [k][row]
    __shared__ float Bs[16][64];   // [k][col]
    int tid = threadIdx.x;
    int tx = tid & 15;
    int ty = tid >> 4;
    int row0 = blockIdx.x * 128;

    float acc[8][4] = {};

    for (int kt = 0; kt < K; kt += 16) {
#pragma unroll
        for (int j = 0; j < 2; j++) {
            int f4 = tid * 2 + j;
            int r = f4 >> 2;
            int kq = (f4 & 3) * 4;
            int row = row0 + r;
            float4 v = (row < M) ? *(const float4*)&A[(size_t)row * K + kt + kq]
                                 : make_float4(0.f, 0.f, 0.f, 0.f);
            As[kq + 0][r] = v.x;
            As[kq + 1][r] = v.y;
            As[kq + 2][r] = v.z;
            As[kq + 3][r] = v.w;
        }
        {
            int bk = tid >> 4, bc = (tid & 15) * 4;
            *(float4*)&Bs[bk][bc] = *(const float4*)&B[(size_t)(kt + bk) * 64 + bc];
        }
        __syncthreads();
#pragma unroll
        for (int kk = 0; kk < 16; kk++) {
            float4 a0 = *(const float4*)&As[kk][ty * 8];
            float4 a1 = *(const float4*)&As[kk][ty * 8 + 4];
            float4 b  = *(const float4*)&Bs[kk][tx * 4];
            float av[8] = {a0.x, a0.y, a0.z, a0.w, a1.x, a1.y, a1.z, a1.w};
            float bv[4] = {b.x, b.y, b.z, b.w};
#pragma unroll
            for (int i = 0; i < 8; i++)
#pragma unroll
                for (int j = 0; j < 4; j++)
                    acc[i][j] += av[i] * bv[j];
        }
        __syncthreads();
    }
#pragma unroll
    for (int i = 0; i < 8; i++) {
        int row = row0 + ty * 8 + i;
        if (row < M) {
            float4 v = make_float4(acc[i][0], acc[i][1], acc[i][2], acc[i][3]);
            *(float4*)&C[(size_t)row * 64 + tx * 4] = v;
        }
    }
}

// ---------------- CSR gather + self-loop + bias + SELU -> g_h -------------
// 16 threads per node; each owns one float4 slice of the 64-wide feature.
__global__ void k_gather(const float* __restrict__ bias) {
    int t = blockIdx.x * blockDim.x + threadIdx.x;
    if (t >= NN * 16) return;
    int n = t >> 4;
    int q = (t & 15) << 2;

    float d = g_deg[n];
    float dd = d * d;
    float4 v = *(const float4*)&g_xw[(size_t)n * 64 + q];
    float4 acc = make_float4(v.x * dd, v.y * dd, v.z * dd, v.w * dd);

    int s = g_rowptr[n], e2 = g_rowptr[n + 1];
    int i = s;
    // unroll by 2 for MLP
    for (; i + 1 < e2; i += 2) {
        int s0 = g_csrc[i], s1 = g_csrc[i + 1];
        float n0 = g_cnrm[i], n1 = g_cnrm[i + 1];
        float4 u0 = *(const float4*)&g_xw[(size_t)s0 * 64 + q];
        float4 u1 = *(const float4*)&g_xw[(size_t)s1 * 64 + q];
        acc.x += n0 * u0.x + n1 * u1.x;
        acc.y += n0 * u0.y + n1 * u1.y;
        acc.z += n0 * u0.z + n1 * u1.z;
        acc.w += n0 * u0.w + n1 * u1.w;
    }
    if (i < e2) {
        int s0 = g_csrc[i];
        float n0 = g_cnrm[i];
        float4 u0 = *(const float4*)&g_xw[(size_t)s0 * 64 + q];
        acc.x += n0 * u0.x;
        acc.y += n0 * u0.y;
        acc.z += n0 * u0.z;
        acc.w += n0 * u0.w;
    }

    float4 b4 = *(const float4*)&bias[q];
    float4 o;
    o.x = selu_f(acc.x + b4.x);
    o.y = selu_f(acc.y + b4.y);
    o.z = selu_f(acc.z + b4.z);
    o.w = selu_f(acc.w + b4.w);
    *(float4*)&g_h[(size_t)n * 64 + q] = o;
}

// ---------------- fused dense MLP (3x 64x64 SELU + 64x20) + softmax --------
__global__ void k_dense(const float* __restrict__ w0, const float* __restrict__ b0,
                        const float* __restrict__ w1, const float* __restrict__ b1,
                        const float* __restrict__ w2, const float* __restrict__ b2,
                        const float* __restrict__ w3, const float* __restrict__ b3,
                        float* __restrict__ out) {
    __shared__ float Ws[64][64];
    __shared__ float hs[16][64];
    __shared__ float lg[16][20];
    __shared__ float bs[64];

    int tid = threadIdx.x;
    int j = tid & 63, rq = tid >> 6;
    int row0 = blockIdx.x * 16;

    for (int i = tid; i < 16 * 64; i += 256) {
        int r = i >> 6, f = i & 63;
        int row = row0 + r;
        hs[r][f] = (row < NN) ? g_h[(size_t)row * 64 + f] : 0.f;
    }

    const float* Wp[3] = {w0, w1, w2};
    const float* Bp[3] = {b0, b1, b2};

    for (int L = 0; L < 3; L++) {
        __syncthreads();
        for (int i = tid; i < 4096; i += 256) Ws[i >> 6][i & 63] = Wp[L][i];
        if (tid < 64) bs[tid] = Bp[L][tid];
        __syncthreads();
        float acc[4];
#pragma unroll
        for (int i = 0; i < 4; i++) acc[i] = bs[j];
        for (int k = 0; k < 64; k++) {
            float wv = Ws[k][j];
#pragma unroll
            for (int i = 0; i < 4; i++) acc[i] += hs[rq * 4 + i][k] * wv;
        }
        __syncthreads();
#pragma unroll
        for (int i = 0; i < 4; i++) hs[rq * 4 + i][j] = selu_f(acc[i]);
    }

    __syncthreads();
    for (int i = tid; i < 64 * 20; i += 256) Ws[i / 20][i % 20] = w3[i];
    if (tid < 20) bs[tid] = b3[tid];
    __syncthreads();

    if (j < 20) {
        float acc[4];
#pragma unroll
        for (int i = 0; i < 4; i++) acc[i] = bs[j];
        for (int k = 0; k < 64; k++) {
            float wv = Ws[k][j];
#pragma unroll
            for (int i = 0; i < 4; i++) acc[i] += hs[rq * 4 + i][k] * wv;
        }
#pragma unroll
        for (int i = 0; i < 4; i++) lg[rq * 4 + i][j] = acc[i];
    }
    __syncthreads();

    for (int idx = tid; idx < 16 * 20; idx += 256) {
        int r = idx / 20, jj = idx % 20;
        int row = row0 + r;
        if (row < NN) {
            float mx = -1e30f;
#pragma unroll
            for (int k = 0; k < 20; k++) mx = fmaxf(mx, lg[r][k]);
            float s = 0.f;
#pragma unroll
            for (int k = 0; k < 20; k++) s += expf(lg[r][k] - mx);
            out[(size_t)row * 20 + jj] = expf(lg[r][jj] - mx) / s;
        }
    }
}

// ---------------- launch ----------------
extern "C" void kernel_launch(void* const* d_in, const int* in_sizes, int n_in,
                              void* d_out, int out_size) {
    const float* x    = (const float*)d_in[0];
    const int*   ei   = (const int*)d_in[1];      // int32 (JAX x64 disabled)
    const float* ea   = (const float*)d_in[2];
    const float* gc0w = (const float*)d_in[3];
    const float* gc0b = (const float*)d_in[4];
    const float* gc1w = (const float*)d_in[5];
    const float* gc1b = (const float*)d_in[6];
    const float* l0w  = (const float*)d_in[7];
    const float* l0b  = (const float*)d_in[8];
    const float* l1w  = (const float*)d_in[9];
    const float* l1b  = (const float*)d_in[10];
    const float* l2w  = (const float*)d_in[11];
    const float* l2b  = (const float*)d_in[12];
    const float* l3w  = (const float*)d_in[13];
    const float* l3b  = (const float*)d_in[14];
    float*       out  = (float*)d_out;

    float *xw, *h;
    cudaGetSymbolAddress((void**)&xw, g_xw);
    cudaGetSymbolAddress((void**)&h,  g_h);

    const int T = 256;

    // normalization + CSR build (reused by both convs)
    k_deg_init<<<(NN + T - 1) / T, T>>>();
    k_deg_acc<<<(EE + T - 1) / T, T>>>(ei, ea);
    k_dinv<<<(NN + T - 1) / T, T>>>();
    k_scan1<<<NBLK, SCAN_BLK>>>();
    k_scan_top<<<1, 128>>>();
    k_scan_add<<<NBLK, SCAN_BLK>>>();
    k_fill<<<(EE + T - 1) / T, T>>>(ei, ea);

    // conv 0
    k_gemm128<<<(NN + 127) / 128, T>>>(x, gc0w, xw, NN, IND);
    k_gather<<<(NN * 16 + T - 1) / T, T>>>(gc0b);

    // conv 1
    k_gemm128<<<(NN + 127) / 128, T>>>(h, gc1w, xw, NN, HGD);
    k_gather<<<(NN * 16 + T - 1) / T, T>>>(gc1b);

    // dense stack + softmax
    k_dense<<<(NN + 15) / 16, T>>>(l0w, l0b, l1w, l1b, l2w, l2b, l3w, l3b, out);
}